// round 12
// baseline (speedup 1.0000x reference)
#include <cuda_runtime.h>
#include <cuda_fp16.h>
#include <stdint.h>

// ============================================================================
// B=1024, F=64, D=64.
//   layer: h'[o,d] = relu(b[o] + sum_{i,j} W[o,i*64+j] * x[i,d] * h[j,d])
//   out[b] = bfc + sum_o Wfc[o]*sum_d h1 + sum_o Wfc[64+o]*sum_d h2
//
// h-stationary HMMA (mma.sync m16n8k16 f16->f32), barrier-free mainloop:
//   per chunk i:  G[i&1] = fp16(W_i) @ fp16(h)       (32 MMAs/warp)
//                 acc += x[i-1,d] * G[(i-1)&1]       (interleaved, 8 FFMA/kk)
// Cross-chunk G ping-pong removes the serial MMA->FFMA window (R10: tensor
// stuck at 45%). Register budget paid by demoting Bh from 32 persistent regs
// to a 16-reg per-kk LDSM double-buffer reload out of smem (h is stationary).
// Single fp16 W and h (R10 measured rel_err 1.03e-4, 10x margin).
// W pre-converted + pre-arranged in mma-A fragment order; coalesced LDG.128,
// double-buffered. CTA = 1 batch, 128 threads (2mh x 2nh, m32n32), 3 CTAs/SM.
// ============================================================================

#define HH_OFF   0            // h fp16 [j*144B], 64 rows = 9216
#define XS_OFF   9216         // x fp32 [i*68 + d] = 17408
#define POOL_OFF 26624
#define SMEM_TOTAL 26688

// W in fragment order: index ((c*2 + mh)*8 + q)*32 + lane, q = kk*2 + m
__device__ __align__(16) uint4 g_Wf[65536];   // 1 MB

// ---------------------------------------------------------------------------
static __device__ __forceinline__ uint32_t s2u(const void* p) {
    uint32_t a;
    asm("{ .reg .u64 t; cvta.to.shared.u64 t, %1; cvt.u32.u64 %0, t; }"
        : "=r"(a) : "l"(p));
    return a;
}
static __device__ __forceinline__ uint32_t h2bits(__half2 h) {
    return *reinterpret_cast<uint32_t*>(&h);
}

#define LDSM4T(r, addr) \
    asm volatile("ldmatrix.sync.aligned.m8n8.x4.trans.shared.b16 {%0,%1,%2,%3}, [%4];" \
                 : "=r"((r)[0]), "=r"((r)[1]), "=r"((r)[2]), "=r"((r)[3]) \
                 : "r"(addr))
#define MMAH(c, a, b0, b1) \
    asm volatile("mma.sync.aligned.m16n8k16.row.col.f32.f16.f16.f32 " \
                 "{%0,%1,%2,%3},{%4,%5,%6,%7},{%8,%9},{%0,%1,%2,%3};" \
                 : "+f"((c)[0]), "+f"((c)[1]), "+f"((c)[2]), "+f"((c)[3]) \
                 : "r"((a)[0]), "r"((a)[1]), "r"((a)[2]), "r"((a)[3]), \
                   "r"(b0), "r"(b1))
#define MMAHZ(c, a, b0, b1) \
    asm volatile("mma.sync.aligned.m16n8k16.row.col.f32.f16.f16.f32 " \
                 "{%0,%1,%2,%3},{%4,%5,%6,%7},{%8,%9},{%10,%10,%10,%10};" \
                 : "=f"((c)[0]), "=f"((c)[1]), "=f"((c)[2]), "=f"((c)[3]) \
                 : "r"((a)[0]), "r"((a)[1]), "r"((a)[2]), "r"((a)[3]), \
                   "r"(b0), "r"(b1), "f"(0.0f))

// ---------------------------------------------------------------------------
// Prologue: W -> fp16 in mma-A fragment order.
__global__ void CIN_52553219834054_wsplit(const float* __restrict__ W1,
                                          const float* __restrict__ W2) {
    const int idx = blockIdx.x * 256 + threadIdx.x;    // 0..65535
    const int c    = idx >> 9;
    const int rem  = idx & 511;
    const int mh   = rem >> 8;
    const int rem2 = rem & 255;
    const int q    = rem2 >> 5;
    const int lane = rem2 & 31;
    const int kk = q >> 1, m = q & 1;
    const int l = c >> 6, i = c & 63;
    const float* __restrict__ W = l ? W2 : W1;
    const int r = lane >> 2, tg = lane & 3;

    uint32_t regs[4];
    #pragma unroll
    for (int e = 0; e < 4; ++e) {
        const int row = mh * 32 + m * 16 + r + (e & 1) * 8;
        const int j   = kk * 16 + tg * 2 + (e >> 1) * 8;
        const float v0 = W[row * 4096 + i * 64 + j];
        const float v1 = W[row * 4096 + i * 64 + j + 1];
        regs[e] = h2bits(__floats2half2_rn(v0, v1));   // .x = v0 (low bits)
    }
    g_Wf[idx] = make_uint4(regs[0], regs[1], regs[2], regs[3]);
}

// ---------------------------------------------------------------------------
__global__ __launch_bounds__(128, 3) void CIN_52553219834054_kernel(
    const float* __restrict__ x,
    const float* __restrict__ b1, const float* __restrict__ b2,
    const float* __restrict__ Wfc, const float* __restrict__ bfc,
    float* __restrict__ out)
{
    extern __shared__ __align__(16) char smem[];
    const uint32_t sb = s2u(smem);
    const int tid = threadIdx.x, wid = tid >> 5, lane = tid & 31;
    const int mh = wid >> 1;          // m-half (rows mh*32..+31)
    const int nh = wid & 1;           // n-half (cols nh*32..+31)

    // ---- init: x -> XS fp32; h0 = fp16(x) ----
    {
        const float4* xg = (const float4*)(x + (size_t)blockIdx.x * 4096);
        float* XSf = (float*)(smem + XS_OFF);
        char* hb = smem + HH_OFF;
        #pragma unroll
        for (int t = 0; t < 8; ++t) {
            const int q = tid + t * 128;            // 0..1023
            const int i = q >> 4, d4 = (q & 15) * 4;
            const float4 v = xg[q];
            *(float4*)(XSf + i * 68 + d4) = v;
            *(uint2*)(hb + i * 144 + d4 * 2) =
                make_uint2(h2bits(__floats2half2_rn(v.x, v.y)),
                           h2bits(__floats2half2_rn(v.z, v.w)));
        }
    }
    __syncthreads();

    // h LDSM base for this warp: + kk*2304 + g*32
    const uint32_t hbase = sb + HH_OFF + (lane & 15) * 144
                         + ((lane >> 4) << 4) + (nh * 2) * 32;
    const uint4* __restrict__ wfp = &g_Wf[mh * 256 + lane];  // + c*512 + kk*64
    const float* __restrict__ xcol = (const float*)(smem + XS_OFF)
                                   + nh * 32 + (lane & 3) * 2;

    // A-fragment double buffer: [buf][m]
    uint4 A[2][2];
    {   // preload chunk 0, kk 0
        A[0][0] = __ldg(wfp); A[0][1] = __ldg(wfp + 32);
    }

    float pool = 0.0f;

    #pragma unroll 1
    for (int l = 0; l < 2; ++l) {
        // ---- Bh double buffer: preload kk = 0 ----
        uint32_t bh[2][2][4];
        LDSM4T(bh[0][0], hbase);
        LDSM4T(bh[0][1], hbase + 32);

        float acc[2][4][4];
        #pragma unroll
        for (int m = 0; m < 2; ++m)
            #pragma unroll
            for (int np = 0; np < 4; ++np)
                #pragma unroll
                for (int e = 0; e < 4; ++e) acc[m][np][e] = 0.0f;

        float G[2][2][4][4];   // ping-pong across chunks

        #pragma unroll 1
        for (int i = 0; i < 64; ++i) {
            const int c = l * 64 + i;
            const int cu = i & 1, pu = cu ^ 1;

            #pragma unroll
            for (int kk = 0; kk < 4; ++kk) {
                // prefetch next (chunk, kk) A-fragments
                {
                    const int nkk = (kk + 1) & 3;
                    const int nc  = (kk == 3) ? c + 1 : c;
                    if (nc < 128) {
                        const uint4* p = wfp + nc * 512 + nkk * 64;
                        uint4* dst = A[(kk + 1) & 1];
                        dst[0] = __ldg(p); dst[1] = __ldg(p + 32);
                    }
                }
                // prefetch Bh for next kk (wraps to kk=0 -> same layer h)
                {
                    const int nkk = (kk + 1) & 3;
                    const uint32_t ad = hbase + nkk * 2304;
                    LDSM4T(bh[(kk + 1) & 1][0], ad);
                    LDSM4T(bh[(kk + 1) & 1][1], ad + 32);
                }
                const uint32_t* Ah[2] = { (const uint32_t*)&A[kk & 1][0],
                                          (const uint32_t*)&A[kk & 1][1] };
                const uint32_t (*bc)[4] = bh[kk & 1];
                #pragma unroll
                for (int m = 0; m < 2; ++m)
                    #pragma unroll
                    for (int np = 0; np < 4; ++np) {
                        const int g = np >> 1, pr = (np & 1) * 2;
                        const uint32_t b0 = bc[g][pr];
                        const uint32_t b1 = bc[g][pr + 1];
                        if (kk == 0) { MMAHZ(G[cu][m][np], Ah[m], b0, b1); }
                        else         { MMAH (G[cu][m][np], Ah[m], b0, b1); }
                    }

                // interleaved x-scaling of PREVIOUS chunk, np = kk
                if (i > 0) {
                    const float2 xv =
                        *(const float2*)(xcol + (i - 1) * 68 + kk * 8);
                    #pragma unroll
                    for (int m = 0; m < 2; ++m) {
                        acc[m][kk][0] += xv.x * G[pu][m][kk][0];
                        acc[m][kk][1] += xv.y * G[pu][m][kk][1];
                        acc[m][kk][2] += xv.x * G[pu][m][kk][2];
                        acc[m][kk][3] += xv.y * G[pu][m][kk][3];
                    }
                }
            }
        }
        // flush chunk 63 (buffer 1)
        #pragma unroll
        for (int np = 0; np < 4; ++np) {
            const float2 xv = *(const float2*)(xcol + 63 * 68 + np * 8);
            #pragma unroll
            for (int m = 0; m < 2; ++m) {
                acc[m][np][0] += xv.x * G[1][m][np][0];
                acc[m][np][1] += xv.y * G[1][m][np][1];
                acc[m][np][2] += xv.x * G[1][m][np][2];
                acc[m][np][3] += xv.y * G[1][m][np][3];
            }
        }
        __syncthreads();   // all h reads (LDSM) done before epilogue rewrites h

        // ---- epilogue: bias + relu, pool, write next h (fp16) ----
        {
            const float* bg = l ? b2 : b1;
            const int d0 = nh * 32 + (lane & 3) * 2;
            char* hb = smem + HH_OFF;
            float ps = 0.0f;
            #pragma unroll
            for (int m = 0; m < 2; ++m) {
                const int o_lo = mh * 32 + m * 16 + (lane >> 2);
                const int o_hi = o_lo + 8;
                const float blv = bg[o_lo], bhv = bg[o_hi];
                const float wlv = Wfc[l * 64 + o_lo], whv = Wfc[l * 64 + o_hi];
                #pragma unroll
                for (int np = 0; np < 4; ++np) {
                    const int d = d0 + np * 8;
                    float v0 = fmaxf(acc[m][np][0] + blv, 0.0f);
                    float v1 = fmaxf(acc[m][np][1] + blv, 0.0f);
                    float v2 = fmaxf(acc[m][np][2] + bhv, 0.0f);
                    float v3 = fmaxf(acc[m][np][3] + bhv, 0.0f);
                    ps += wlv * (v0 + v1) + whv * (v2 + v3);
                    if (l == 0) {
                        *(uint32_t*)(hb + o_lo * 144 + d * 2) =
                            h2bits(__floats2half2_rn(v0, v1));
                        *(uint32_t*)(hb + o_hi * 144 + d * 2) =
                            h2bits(__floats2half2_rn(v2, v3));
                    }
                }
            }
            pool += ps;
        }
        __syncthreads();   // new h visible before next-layer Bh preload
    }

    // ---- reduce pool across 4 warps, write out ----
    #pragma unroll
    for (int off = 16; off > 0; off >>= 1)
        pool += __shfl_xor_sync(0xffffffffu, pool, off);
    float* pb = (float*)(smem + POOL_OFF);
    if (lane == 0) pb[wid] = pool;
    __syncthreads();
    if (tid == 0)
        out[blockIdx.x] = pb[0] + pb[1] + pb[2] + pb[3] + bfc[0];
}

// ---------------------------------------------------------------------------
extern "C" void kernel_launch(void* const* d_in, const int* in_sizes, int n_in,
                              void* d_out, int out_size) {
    const float* x   = (const float*)d_in[0];
    const float* W1  = (const float*)d_in[1];
    const float* b1  = (const float*)d_in[2];
    const float* W2  = (const float*)d_in[3];
    const float* b2  = (const float*)d_in[4];
    const float* Wfc = (const float*)d_in[5];
    const float* bfc = (const float*)d_in[6];

    cudaFuncSetAttribute(CIN_52553219834054_kernel,
                         cudaFuncAttributeMaxDynamicSharedMemorySize, SMEM_TOTAL);

    CIN_52553219834054_wsplit<<<256, 256>>>(W1, W2);
    CIN_52553219834054_kernel<<<1024, 128, SMEM_TOTAL>>>(
        x, b1, b2, Wfc, bfc, (float*)d_out);
}

// round 13
// speedup vs baseline: 4.3553x; 4.3553x over previous
#include <cuda_runtime.h>
#include <cuda_fp16.h>
#include <stdint.h>

// ============================================================================
// B=1024, F=64, D=64.
//   layer: h'[o,d] = relu(b[o] + sum_{i,j} W[o,i*64+j] * x[i,d] * h[j,d])
//   out[b] = bfc + sum_o Wfc[o]*sum_d h1 + sum_o Wfc[64+o]*sum_d h2
//
// h-stationary HMMA (mma.sync m16n8k16 f16->f32), barrier-free mainloop with
// cross-chunk G ping-pong done RIGHT: two named register arrays G0/G1 and a
// pair-unrolled i-loop so every buffer index is compile-time constant.
// (R8/R12 lesson: G[i&1] under "#pragma unroll 1" = runtime-indexed array =
// local memory, tensor 11%. regs=160 was spilled G, not true demand.)
//   chunk i   -> MMAs into G1 while FFMAs drain chunk i-1 from G0
//   chunk i+1 -> MMAs into G0 while FFMAs drain chunk i   from G1
// Bh per-kk LDSM double-buffer (static [kk&1] indices, fine). Single fp16 W
// and h (measured rel_err 1.03e-4, 10x margin). W pre-arranged in mma-A
// fragment order, coalesced LDG.128 double-buffered. 128 thr, 3 CTAs/SM.
// ============================================================================

#define HH_OFF   0            // h fp16 [j*144B], 64 rows = 9216
#define XS_OFF   9216         // x fp32 [i*68 + d] = 17408
#define POOL_OFF 26624
#define SMEM_TOTAL 26688

// W in fragment order: index ((c*2 + mh)*8 + q)*32 + lane, q = kk*2 + m
__device__ __align__(16) uint4 g_Wf[65536];   // 1 MB

// ---------------------------------------------------------------------------
static __device__ __forceinline__ uint32_t s2u(const void* p) {
    uint32_t a;
    asm("{ .reg .u64 t; cvta.to.shared.u64 t, %1; cvt.u32.u64 %0, t; }"
        : "=r"(a) : "l"(p));
    return a;
}
static __device__ __forceinline__ uint32_t h2bits(__half2 h) {
    return *reinterpret_cast<uint32_t*>(&h);
}

#define LDSM4T(r, addr) \
    asm volatile("ldmatrix.sync.aligned.m8n8.x4.trans.shared.b16 {%0,%1,%2,%3}, [%4];" \
                 : "=r"((r)[0]), "=r"((r)[1]), "=r"((r)[2]), "=r"((r)[3]) \
                 : "r"(addr))
#define MMAH(c, a, b0, b1) \
    asm volatile("mma.sync.aligned.m16n8k16.row.col.f32.f16.f16.f32 " \
                 "{%0,%1,%2,%3},{%4,%5,%6,%7},{%8,%9},{%0,%1,%2,%3};" \
                 : "+f"((c)[0]), "+f"((c)[1]), "+f"((c)[2]), "+f"((c)[3]) \
                 : "r"((a)[0]), "r"((a)[1]), "r"((a)[2]), "r"((a)[3]), \
                   "r"(b0), "r"(b1))
#define MMAHZ(c, a, b0, b1) \
    asm volatile("mma.sync.aligned.m16n8k16.row.col.f32.f16.f16.f32 " \
                 "{%0,%1,%2,%3},{%4,%5,%6,%7},{%8,%9},{%10,%10,%10,%10};" \
                 : "=f"((c)[0]), "=f"((c)[1]), "=f"((c)[2]), "=f"((c)[3]) \
                 : "r"((a)[0]), "r"((a)[1]), "r"((a)[2]), "r"((a)[3]), \
                   "r"(b0), "r"(b1), "f"(0.0f))

// ---------------------------------------------------------------------------
// Prologue: W -> fp16 in mma-A fragment order.
__global__ void CIN_52553219834054_wsplit(const float* __restrict__ W1,
                                          const float* __restrict__ W2) {
    const int idx = blockIdx.x * 256 + threadIdx.x;    // 0..65535
    const int c    = idx >> 9;
    const int rem  = idx & 511;
    const int mh   = rem >> 8;
    const int rem2 = rem & 255;
    const int q    = rem2 >> 5;
    const int lane = rem2 & 31;
    const int kk = q >> 1, m = q & 1;
    const int l = c >> 6, i = c & 63;
    const float* __restrict__ W = l ? W2 : W1;
    const int r = lane >> 2, tg = lane & 3;

    uint32_t regs[4];
    #pragma unroll
    for (int e = 0; e < 4; ++e) {
        const int row = mh * 32 + m * 16 + r + (e & 1) * 8;
        const int j   = kk * 16 + tg * 2 + (e >> 1) * 8;
        const float v0 = W[row * 4096 + i * 64 + j];
        const float v1 = W[row * 4096 + i * 64 + j + 1];
        regs[e] = h2bits(__floats2half2_rn(v0, v1));   // .x = v0 (low bits)
    }
    g_Wf[idx] = make_uint4(regs[0], regs[1], regs[2], regs[3]);
}

// ---------------------------------------------------------------------------
__global__ __launch_bounds__(128, 3) void CIN_52553219834054_kernel(
    const float* __restrict__ x,
    const float* __restrict__ b1, const float* __restrict__ b2,
    const float* __restrict__ Wfc, const float* __restrict__ bfc,
    float* __restrict__ out)
{
    extern __shared__ __align__(16) char smem[];
    const uint32_t sb = s2u(smem);
    const int tid = threadIdx.x, wid = tid >> 5, lane = tid & 31;
    const int mh = wid >> 1;          // m-half (rows mh*32..+31)
    const int nh = wid & 1;           // n-half (cols nh*32..+31)

    // ---- init: x -> XS fp32; h0 = fp16(x) ----
    {
        const float4* xg = (const float4*)(x + (size_t)blockIdx.x * 4096);
        float* XSf = (float*)(smem + XS_OFF);
        char* hb = smem + HH_OFF;
        #pragma unroll
        for (int t = 0; t < 8; ++t) {
            const int q = tid + t * 128;            // 0..1023
            const int i = q >> 4, d4 = (q & 15) * 4;
            const float4 v = xg[q];
            *(float4*)(XSf + i * 68 + d4) = v;
            *(uint2*)(hb + i * 144 + d4 * 2) =
                make_uint2(h2bits(__floats2half2_rn(v.x, v.y)),
                           h2bits(__floats2half2_rn(v.z, v.w)));
        }
    }
    __syncthreads();

    // h LDSM base for this warp: + kk*2304 + g*32
    const uint32_t hbase = sb + HH_OFF + (lane & 15) * 144
                         + ((lane >> 4) << 4) + (nh * 2) * 32;
    const uint4* __restrict__ wfp = &g_Wf[mh * 256 + lane];  // + c*512 + kk*64
    const float* __restrict__ xcol = (const float*)(smem + XS_OFF)
                                   + nh * 32 + (lane & 3) * 2;

    // A-fragment double buffer: [buf][m]
    uint4 A[2][2];
    {   // preload chunk 0, kk 0
        A[0][0] = __ldg(wfp); A[0][1] = __ldg(wfp + 32);
    }

    float pool = 0.0f;

    #pragma unroll 1
    for (int l = 0; l < 2; ++l) {
        // ---- Bh double buffer: preload kk = 0 ----
        uint32_t bh[2][2][4];
        LDSM4T(bh[0][0], hbase);
        LDSM4T(bh[0][1], hbase + 32);

        float acc[2][4][4];
        #pragma unroll
        for (int m = 0; m < 2; ++m)
            #pragma unroll
            for (int np = 0; np < 4; ++np)
                #pragma unroll
                for (int e = 0; e < 4; ++e) acc[m][np][e] = 0.0f;

        float G0[2][4][4], G1[2][4][4];   // named ping-pong (static indices!)

        // one chunk: MMAs into Gc; if SCALE, drain chunk ip from Gp (np = kk)
        auto chunk = [&](int c, float (&Gc)[2][4][4], float (&Gp)[2][4][4],
                         bool SCALE, int ip) {
            #pragma unroll
            for (int kk = 0; kk < 4; ++kk) {
                {   // prefetch next (chunk, kk) A-fragments
                    const int nkk = (kk + 1) & 3;
                    const int nc  = (kk == 3) ? c + 1 : c;
                    if (nc < 128) {
                        const uint4* p = wfp + nc * 512 + nkk * 64;
                        uint4* dst = A[(kk + 1) & 1];
                        dst[0] = __ldg(p); dst[1] = __ldg(p + 32);
                    }
                }
                {   // prefetch Bh for next kk (wraps to kk=0, same-layer h)
                    const int nkk = (kk + 1) & 3;
                    const uint32_t ad = hbase + nkk * 2304;
                    LDSM4T(bh[(kk + 1) & 1][0], ad);
                    LDSM4T(bh[(kk + 1) & 1][1], ad + 32);
                }
                const uint32_t* Ah[2] = { (const uint32_t*)&A[kk & 1][0],
                                          (const uint32_t*)&A[kk & 1][1] };
                const uint32_t (*bc)[4] = bh[kk & 1];
                #pragma unroll
                for (int m = 0; m < 2; ++m)
                    #pragma unroll
                    for (int np = 0; np < 4; ++np) {
                        const int g = np >> 1, pr = (np & 1) * 2;
                        const uint32_t b0 = bc[g][pr];
                        const uint32_t b1 = bc[g][pr + 1];
                        if (kk == 0) { MMAHZ(Gc[m][np], Ah[m], b0, b1); }
                        else         { MMAH (Gc[m][np], Ah[m], b0, b1); }
                    }
                if (SCALE) {   // drain previous chunk, np = kk
                    const float2 xv = *(const float2*)(xcol + ip * 68 + kk * 8);
                    #pragma unroll
                    for (int m = 0; m < 2; ++m) {
                        acc[m][kk][0] += xv.x * Gp[m][kk][0];
                        acc[m][kk][1] += xv.y * Gp[m][kk][1];
                        acc[m][kk][2] += xv.x * Gp[m][kk][2];
                        acc[m][kk][3] += xv.y * Gp[m][kk][3];
                    }
                }
            }
        };

        const int cb = l * 64;
        chunk(cb, G0, G1, false, 0);             // chunk 0 -> G0
        #pragma unroll 1
        for (int i = 1; i < 63; i += 2) {        // pairs (1..62)
            chunk(cb + i,     G1, G0, true, i - 1);
            chunk(cb + i + 1, G0, G1, true, i);
        }
        chunk(cb + 63, G1, G0, true, 62);        // chunk 63 -> G1
        // flush chunk 63 from G1
        #pragma unroll
        for (int np = 0; np < 4; ++np) {
            const float2 xv = *(const float2*)(xcol + 63 * 68 + np * 8);
            #pragma unroll
            for (int m = 0; m < 2; ++m) {
                acc[m][np][0] += xv.x * G1[m][np][0];
                acc[m][np][1] += xv.y * G1[m][np][1];
                acc[m][np][2] += xv.x * G1[m][np][2];
                acc[m][np][3] += xv.y * G1[m][np][3];
            }
        }
        __syncthreads();   // all h reads (LDSM) done before epilogue rewrites h

        // ---- epilogue: bias + relu, pool, write next h (fp16) ----
        {
            const float* bg = l ? b2 : b1;
            const int d0 = nh * 32 + (lane & 3) * 2;
            char* hb = smem + HH_OFF;
            float ps = 0.0f;
            #pragma unroll
            for (int m = 0; m < 2; ++m) {
                const int o_lo = mh * 32 + m * 16 + (lane >> 2);
                const int o_hi = o_lo + 8;
                const float blv = bg[o_lo], bhv = bg[o_hi];
                const float wlv = Wfc[l * 64 + o_lo], whv = Wfc[l * 64 + o_hi];
                #pragma unroll
                for (int np = 0; np < 4; ++np) {
                    const int d = d0 + np * 8;
                    float v0 = fmaxf(acc[m][np][0] + blv, 0.0f);
                    float v1 = fmaxf(acc[m][np][1] + blv, 0.0f);
                    float v2 = fmaxf(acc[m][np][2] + bhv, 0.0f);
                    float v3 = fmaxf(acc[m][np][3] + bhv, 0.0f);
                    ps += wlv * (v0 + v1) + whv * (v2 + v3);
                    if (l == 0) {
                        *(uint32_t*)(hb + o_lo * 144 + d * 2) =
                            h2bits(__floats2half2_rn(v0, v1));
                        *(uint32_t*)(hb + o_hi * 144 + d * 2) =
                            h2bits(__floats2half2_rn(v2, v3));
                    }
                }
            }
            pool += ps;
        }
        __syncthreads();   // new h visible before next-layer Bh preload
    }

    // ---- reduce pool across 4 warps, write out ----
    #pragma unroll
    for (int off = 16; off > 0; off >>= 1)
        pool += __shfl_xor_sync(0xffffffffu, pool, off);
    float* pb = (float*)(smem + POOL_OFF);
    if (lane == 0) pb[wid] = pool;
    __syncthreads();
    if (tid == 0)
        out[blockIdx.x] = pb[0] + pb[1] + pb[2] + pb[3] + bfc[0];
}

// ---------------------------------------------------------------------------
extern "C" void kernel_launch(void* const* d_in, const int* in_sizes, int n_in,
                              void* d_out, int out_size) {
    const float* x   = (const float*)d_in[0];
    const float* W1  = (const float*)d_in[1];
    const float* b1  = (const float*)d_in[2];
    const float* W2  = (const float*)d_in[3];
    const float* b2  = (const float*)d_in[4];
    const float* Wfc = (const float*)d_in[5];
    const float* bfc = (const float*)d_in[6];

    cudaFuncSetAttribute(CIN_52553219834054_kernel,
                         cudaFuncAttributeMaxDynamicSharedMemorySize, SMEM_TOTAL);

    CIN_52553219834054_wsplit<<<256, 256>>>(W1, W2);
    CIN_52553219834054_kernel<<<1024, 128, SMEM_TOTAL>>>(
        x, b1, b2, Wfc, bfc, (float*)d_out);
}

// round 14
// speedup vs baseline: 5.5264x; 1.2689x over previous
#include <cuda_runtime.h>
#include <cuda_fp16.h>
#include <stdint.h>

// ============================================================================
// B=1024, F=64, D=64.
//   layer: h'[o,d] = relu(b[o] + sum_{i,j} W[o,i*64+j] * x[i,d] * h[j,d])
//   out[b] = bfc + sum_o Wfc[o]*sum_d h1 + sum_o Wfc[64+o]*sum_d h2
//
// x-folded h-stationary HMMA (mma.sync m16n8k16 f16->f32):
//   acc += W_i @ (h * x[i,:])    -- x-scaling folded into the B operand.
// Each B-frag reg holds 2 j-values at ONE d per lane, so the scaling is one
// mul.rn.f16x2 against a per-lane x splat. MMAs accumulate DIRECTLY into acc:
// no G buffer, no FFMA drain, no per-chunk serial window (R10-R13 lesson: the
// G+drain structure was the bottleneck, not its scheduling).
// Per chunk/warp: 4 LDS.32 (x) + 4 cvt splats + 32 HMUL2 + 32 MMA + 8 LDG.
// Single fp16 W and h; one extra fp16 rounding on z -> rel_err ~1.3e-4.
// Bh persistent in registers per layer (R13: per-kk reload hurt L1).
// W pre-arranged in mma-A fragment order; coalesced LDG.128 double-buffered.
// CTA = 1 batch, 128 threads (2mh x 2nh, m32n32), regs ~110 -> 4 CTAs/SM:
// 4 warps/SMSP and 1.73 waves (R10 tail was 31%-full third wave).
// ============================================================================

#define HH_OFF   0            // h fp16 [j*144B], 64 rows = 9216
#define XS_OFF   9216         // x fp32 [i*68 + d] = 17408
#define POOL_OFF 26624
#define SMEM_TOTAL 26688

// W in fragment order: index ((c*2 + mh)*8 + q)*32 + lane, q = kk*2 + m
__device__ __align__(16) uint4 g_Wf[65536];   // 1 MB

// ---------------------------------------------------------------------------
static __device__ __forceinline__ uint32_t s2u(const void* p) {
    uint32_t a;
    asm("{ .reg .u64 t; cvta.to.shared.u64 t, %1; cvt.u32.u64 %0, t; }"
        : "=r"(a) : "l"(p));
    return a;
}
static __device__ __forceinline__ uint32_t h2bits(__half2 h) {
    return *reinterpret_cast<uint32_t*>(&h);
}

#define LDSM4T(r, addr) \
    asm volatile("ldmatrix.sync.aligned.m8n8.x4.trans.shared.b16 {%0,%1,%2,%3}, [%4];" \
                 : "=r"((r)[0]), "=r"((r)[1]), "=r"((r)[2]), "=r"((r)[3]) \
                 : "r"(addr))
#define MMAH(c, a, b0, b1) \
    asm volatile("mma.sync.aligned.m16n8k16.row.col.f32.f16.f16.f32 " \
                 "{%0,%1,%2,%3},{%4,%5,%6,%7},{%8,%9},{%0,%1,%2,%3};" \
                 : "+f"((c)[0]), "+f"((c)[1]), "+f"((c)[2]), "+f"((c)[3]) \
                 : "r"((a)[0]), "r"((a)[1]), "r"((a)[2]), "r"((a)[3]), \
                   "r"(b0), "r"(b1))
#define MMAHZ(c, a, b0, b1) \
    asm volatile("mma.sync.aligned.m16n8k16.row.col.f32.f16.f16.f32 " \
                 "{%0,%1,%2,%3},{%4,%5,%6,%7},{%8,%9},{%10,%10,%10,%10};" \
                 : "=f"((c)[0]), "=f"((c)[1]), "=f"((c)[2]), "=f"((c)[3]) \
                 : "r"((a)[0]), "r"((a)[1]), "r"((a)[2]), "r"((a)[3]), \
                   "r"(b0), "r"(b1), "f"(0.0f))
#define HMUL2(d, a, b) \
    asm("mul.rn.f16x2 %0, %1, %2;" : "=r"(d) : "r"(a), "r"(b))
#define SPLATH2(d, f) \
    asm("cvt.rn.f16x2.f32 %0, %1, %1;" : "=r"(d) : "f"(f))

// ---------------------------------------------------------------------------
// Prologue: W -> fp16 in mma-A fragment order.
__global__ void CIN_52553219834054_wsplit(const float* __restrict__ W1,
                                          const float* __restrict__ W2) {
    const int idx = blockIdx.x * 256 + threadIdx.x;    // 0..65535
    const int c    = idx >> 9;
    const int rem  = idx & 511;
    const int mh   = rem >> 8;
    const int rem2 = rem & 255;
    const int q    = rem2 >> 5;
    const int lane = rem2 & 31;
    const int kk = q >> 1, m = q & 1;
    const int l = c >> 6, i = c & 63;
    const float* __restrict__ W = l ? W2 : W1;
    const int r = lane >> 2, tg = lane & 3;

    uint32_t regs[4];
    #pragma unroll
    for (int e = 0; e < 4; ++e) {
        const int row = mh * 32 + m * 16 + r + (e & 1) * 8;
        const int j   = kk * 16 + tg * 2 + (e >> 1) * 8;
        const float v0 = W[row * 4096 + i * 64 + j];
        const float v1 = W[row * 4096 + i * 64 + j + 1];
        regs[e] = h2bits(__floats2half2_rn(v0, v1));   // .x = v0 (low bits)
    }
    g_Wf[idx] = make_uint4(regs[0], regs[1], regs[2], regs[3]);
}

// ---------------------------------------------------------------------------
__global__ __launch_bounds__(128, 4) void CIN_52553219834054_kernel(
    const float* __restrict__ x,
    const float* __restrict__ b1, const float* __restrict__ b2,
    const float* __restrict__ Wfc, const float* __restrict__ bfc,
    float* __restrict__ out)
{
    extern __shared__ __align__(16) char smem[];
    const uint32_t sb = s2u(smem);
    const int tid = threadIdx.x, wid = tid >> 5, lane = tid & 31;
    const int mh = wid >> 1;          // m-half (rows mh*32..+31)
    const int nh = wid & 1;           // n-half (cols nh*32..+31)

    // ---- init: x -> XS fp32; h0 = fp16(x) ----
    {
        const float4* xg = (const float4*)(x + (size_t)blockIdx.x * 4096);
        float* XSf = (float*)(smem + XS_OFF);
        char* hb = smem + HH_OFF;
        #pragma unroll
        for (int t = 0; t < 8; ++t) {
            const int q = tid + t * 128;            // 0..1023
            const int i = q >> 4, d4 = (q & 15) * 4;
            const float4 v = xg[q];
            *(float4*)(XSf + i * 68 + d4) = v;
            *(uint2*)(hb + i * 144 + d4 * 2) =
                make_uint2(h2bits(__floats2half2_rn(v.x, v.y)),
                           h2bits(__floats2half2_rn(v.z, v.w)));
        }
    }
    __syncthreads();

    // h LDSM base for this warp: + kk*2304 + g*32
    const uint32_t hbase = sb + HH_OFF + (lane & 15) * 144
                         + ((lane >> 4) << 4) + (nh * 2) * 32;
    const uint4* __restrict__ wfp = &g_Wf[mh * 256 + lane];  // + c*512 + kk*64
    // x for the B-frag scaling: lane's d values are nh*32 + np*8 + (lane>>2)
    const float* __restrict__ xcol = (const float*)(smem + XS_OFF)
                                   + nh * 32 + (lane >> 2);

    // A-fragment double buffer: [buf][m]
    uint4 A[2][2];
    {   // preload chunk 0, kk 0
        A[0][0] = __ldg(wfp); A[0][1] = __ldg(wfp + 32);
    }

    float pool = 0.0f;

    #pragma unroll 1
    for (int l = 0; l < 2; ++l) {
        // ---- h B-fragments (fp16) into registers, once per layer ----
        uint32_t Bh[4][2][4];
        {
            #pragma unroll
            for (int kk = 0; kk < 4; ++kk)
                #pragma unroll
                for (int g = 0; g < 2; ++g)
                    LDSM4T(Bh[kk][g], hbase + kk * 2304 + g * 32);
        }
        __syncthreads();   // all B-frags read before epilogue may rewrite h

        float acc[2][4][4];

        #pragma unroll 1
        for (int i = 0; i < 64; ++i) {
            const int c = l * 64 + i;

            // x splats for this chunk: one per np (d = nh*32 + np*8 + lane>>2)
            uint32_t xs2[4];
            #pragma unroll
            for (int np = 0; np < 4; ++np)
                SPLATH2(xs2[np], xcol[i * 68 + np * 8]);

            #pragma unroll
            for (int kk = 0; kk < 4; ++kk) {
                // prefetch next (chunk, kk) A-fragments
                {
                    const int nkk = (kk + 1) & 3;
                    const int nc  = (kk == 3) ? c + 1 : c;
                    if (nc < 128) {
                        const uint4* p = wfp + nc * 512 + nkk * 64;
                        uint4* dst = A[(kk + 1) & 1];
                        dst[0] = __ldg(p); dst[1] = __ldg(p + 32);
                    }
                }
                // scale B-frags by x (one f16x2 mul per reg)
                uint32_t zb[4][2];
                #pragma unroll
                for (int np = 0; np < 4; ++np) {
                    const int g = np >> 1, pr = (np & 1) * 2;
                    HMUL2(zb[np][0], Bh[kk][g][pr],     xs2[np]);
                    HMUL2(zb[np][1], Bh[kk][g][pr + 1], xs2[np]);
                }
                const uint32_t* Ah[2] = { (const uint32_t*)&A[kk & 1][0],
                                          (const uint32_t*)&A[kk & 1][1] };
                #pragma unroll
                for (int m = 0; m < 2; ++m)
                    #pragma unroll
                    for (int np = 0; np < 4; ++np) {
                        if (i == 0 && kk == 0) {
                            MMAHZ(acc[m][np], Ah[m], zb[np][0], zb[np][1]);
                        } else {
                            MMAH (acc[m][np], Ah[m], zb[np][0], zb[np][1]);
                        }
                    }
            }
        }
        __syncthreads();   // all h reads done before epilogue rewrites h

        // ---- epilogue: bias + relu, pool, write next h (fp16) ----
        {
            const float* bg = l ? b2 : b1;
            const int d0 = nh * 32 + (lane & 3) * 2;
            char* hb = smem + HH_OFF;
            float ps = 0.0f;
            #pragma unroll
            for (int m = 0; m < 2; ++m) {
                const int o_lo = mh * 32 + m * 16 + (lane >> 2);
                const int o_hi = o_lo + 8;
                const float blv = bg[o_lo], bhv = bg[o_hi];
                const float wlv = Wfc[l * 64 + o_lo], whv = Wfc[l * 64 + o_hi];
                #pragma unroll
                for (int np = 0; np < 4; ++np) {
                    const int d = d0 + np * 8;
                    float v0 = fmaxf(acc[m][np][0] + blv, 0.0f);
                    float v1 = fmaxf(acc[m][np][1] + blv, 0.0f);
                    float v2 = fmaxf(acc[m][np][2] + bhv, 0.0f);
                    float v3 = fmaxf(acc[m][np][3] + bhv, 0.0f);
                    ps += wlv * (v0 + v1) + whv * (v2 + v3);
                    if (l == 0) {
                        *(uint32_t*)(hb + o_lo * 144 + d * 2) =
                            h2bits(__floats2half2_rn(v0, v1));
                        *(uint32_t*)(hb + o_hi * 144 + d * 2) =
                            h2bits(__floats2half2_rn(v2, v3));
                    }
                }
            }
            pool += ps;
        }
        __syncthreads();   // new h visible before next-layer Bh load
    }

    // ---- reduce pool across 4 warps, write out ----
    #pragma unroll
    for (int off = 16; off > 0; off >>= 1)
        pool += __shfl_xor_sync(0xffffffffu, pool, off);
    float* pb = (float*)(smem + POOL_OFF);
    if (lane == 0) pb[wid] = pool;
    __syncthreads();
    if (tid == 0)
        out[blockIdx.x] = pb[0] + pb[1] + pb[2] + pb[3] + bfc[0];
}

// ---------------------------------------------------------------------------
extern "C" void kernel_launch(void* const* d_in, const int* in_sizes, int n_in,
                              void* d_out, int out_size) {
    const float* x   = (const float*)d_in[0];
    const float* W1  = (const float*)d_in[1];
    const float* b1  = (const float*)d_in[2];
    const float* W2  = (const float*)d_in[3];
    const float* b2  = (const float*)d_in[4];
    const float* Wfc = (const float*)d_in[5];
    const float* bfc = (const float*)d_in[6];

    cudaFuncSetAttribute(CIN_52553219834054_kernel,
                         cudaFuncAttributeMaxDynamicSharedMemorySize, SMEM_TOTAL);

    CIN_52553219834054_wsplit<<<256, 256>>>(W1, W2);
    CIN_52553219834054_kernel<<<1024, 128, SMEM_TOTAL>>>(
        x, b1, b2, Wfc, bfc, (float*)d_out);
}